// round 10
// baseline (speedup 1.0000x reference)
#include <cuda_runtime.h>
#include <cuda_bf16.h>
#include <math.h>

typedef unsigned long long ull;
typedef __nv_bfloat16 bf16;

#define D_IN  1024
#define NEXP  8
#define HID   4096
#define H2    8192
#define NTOK  4096
#define PMAX  9216     // 8192 pairs + per-expert padding to 128

// GEMM tiling: 256 threads, K-chunk 64 (128B rows = SW128 atom)
#define TM    128
#define KC    64
#define A_TILE 16384          // 128 rows * 128B
#define B_TILE 32768          // 256 rows * 128B
#define STAGE  (2*A_TILE + 2*B_TILE)   // 96KB
#define SMEM_GEMM (2 * STAGE)          // 192KB double buffer

// ---------------- scratch (static device memory: allowed) ----------------
__device__ float g_yp[(size_t)PMAX * D_IN];   // per-pair expert out fp32
__device__ bf16 g_xh[(size_t)PMAX * D_IN];
__device__ bf16 g_xl[(size_t)PMAX * D_IN];
__device__ bf16 g_ah[(size_t)PMAX * HID];
__device__ bf16 g_al[(size_t)PMAX * HID];
__device__ float g_probs[NTOK * NEXP];
__device__ int   g_top_idx[NTOK * 2];
__device__ float g_top_w[NTOK * 2];
__device__ int   g_counts[NEXP];
__device__ int   g_cursor[NEXP];
__device__ int   g_off[NEXP + 1];
__device__ int   g_pair_token[PMAX];
__device__ int   g_pair_slot[NTOK * 2];

// ---------------- PTX helpers (baseline sm_80+, safe for sm_103 target) --
__device__ __forceinline__ unsigned smem_u32(const void* p) {
    unsigned a;
    asm("{ .reg .u64 t; cvta.to.shared.u64 t, %1; cvt.u32.u64 %0, t; }" : "=r"(a) : "l"(p));
    return a;
}
__device__ __forceinline__ void cpa16(unsigned dst, const void* src) {
    asm volatile("cp.async.cg.shared.global [%0], [%1], 16;" :: "r"(dst), "l"(src));
}
__device__ __forceinline__ void ldm4(unsigned* r, unsigned addr) {
    asm volatile("ldmatrix.sync.aligned.m8n8.x4.shared.b16 {%0,%1,%2,%3}, [%4];"
                 : "=r"(r[0]), "=r"(r[1]), "=r"(r[2]), "=r"(r[3]) : "r"(addr));
}
#define MMA(d, a, b) \
    asm volatile("mma.sync.aligned.m16n8k16.row.col.f32.bf16.bf16.f32 " \
        "{%0,%1,%2,%3}, {%4,%5,%6,%7}, {%8,%9}, {%0,%1,%2,%3};" \
        : "+f"((d)[0]), "+f"((d)[1]), "+f"((d)[2]), "+f"((d)[3]) \
        : "r"((a)[0]), "r"((a)[1]), "r"((a)[2]), "r"((a)[3]), "r"((b)[0]), "r"((b)[1]))

__device__ __forceinline__ unsigned sw128(unsigned bo) { return bo ^ ((bo >> 3) & 0x70); }

__device__ __forceinline__ void split_store4(float4 v, __nv_bfloat162* hi, __nv_bfloat162* lo) {
    bf16 h0 = __float2bfloat16(v.x), h1 = __float2bfloat16(v.y);
    bf16 h2 = __float2bfloat16(v.z), h3 = __float2bfloat16(v.w);
    hi[0] = __halves2bfloat162(h0, h1);
    hi[1] = __halves2bfloat162(h2, h3);
    lo[0] = __floats2bfloat162_rn(v.x - __bfloat162float(h0), v.y - __bfloat162float(h1));
    lo[1] = __floats2bfloat162_rn(v.z - __bfloat162float(h2), v.w - __bfloat162float(h3));
}
__device__ __forceinline__ void split2(float a0, float a1,
                                       __nv_bfloat162* ph, __nv_bfloat162* pl) {
    bf16 h0 = __float2bfloat16(a0), h1 = __float2bfloat16(a1);
    *ph = __halves2bfloat162(h0, h1);
    *pl = __floats2bfloat162_rn(a0 - __bfloat162float(h0), a1 - __bfloat162float(h1));
}
__device__ __forceinline__ float silu(float g) { return g / (1.f + expf(-g)); }

// fp32x4 -> bf16 hi/lo, stored to swizzled smem (8B each)
__device__ __forceinline__ void split4_sts(float4 v, unsigned dhi, unsigned dlo) {
    bf16 h0 = __float2bfloat16(v.x), h1 = __float2bfloat16(v.y);
    bf16 h2 = __float2bfloat16(v.z), h3 = __float2bfloat16(v.w);
    unsigned u0 = (unsigned)__bfloat16_as_ushort(h0) | ((unsigned)__bfloat16_as_ushort(h1) << 16);
    unsigned u1 = (unsigned)__bfloat16_as_ushort(h2) | ((unsigned)__bfloat16_as_ushort(h3) << 16);
    bf16 l0 = __float2bfloat16(v.x - __bfloat162float(h0));
    bf16 l1 = __float2bfloat16(v.y - __bfloat162float(h1));
    bf16 l2 = __float2bfloat16(v.z - __bfloat162float(h2));
    bf16 l3 = __float2bfloat16(v.w - __bfloat162float(h3));
    unsigned w0 = (unsigned)__bfloat16_as_ushort(l0) | ((unsigned)__bfloat16_as_ushort(l1) << 16);
    unsigned w1 = (unsigned)__bfloat16_as_ushort(l2) | ((unsigned)__bfloat16_as_ushort(l3) << 16);
    asm volatile("st.shared.v2.b32 [%0], {%1,%2};" :: "r"(dhi), "r"(u0), "r"(u1) : "memory");
    asm volatile("st.shared.v2.b32 [%0], {%1,%2};" :: "r"(dlo), "r"(w0), "r"(w1) : "memory");
}

// ---------------- 1. init ----------------
__global__ void init_k() {
    int i = blockIdx.x * blockDim.x + threadIdx.x;
    if (i < NEXP) { g_counts[i] = 0; g_cursor[i] = 0; }
    if (i < PMAX) g_pair_token[i] = -1;
}

// ---------------- 2. gate ----------------
__global__ void gate_k(const float* __restrict__ x, const float* __restrict__ Wg) {
    int t    = (blockIdx.x * blockDim.x + threadIdx.x) >> 5;
    int lane = threadIdx.x & 31;
    if (t >= NTOK) return;
    const float* xr = x + (size_t)t * D_IN;
    float acc[NEXP];
#pragma unroll
    for (int e = 0; e < NEXP; e++) acc[e] = 0.f;
    for (int d = lane; d < D_IN; d += 32) {
        float xv = xr[d];
        const float* wr = Wg + d * NEXP;
#pragma unroll
        for (int e = 0; e < NEXP; e++) acc[e] = fmaf(xv, wr[e], acc[e]);
    }
#pragma unroll
    for (int off = 16; off; off >>= 1)
#pragma unroll
        for (int e = 0; e < NEXP; e++)
            acc[e] += __shfl_down_sync(0xffffffffu, acc[e], off);
    if (lane == 0) {
        int e0 = 0; float v0 = acc[0];
#pragma unroll
        for (int e = 1; e < NEXP; e++) if (acc[e] > v0) { v0 = acc[e]; e0 = e; }
        int e1 = -1; float v1 = -1e30f;
#pragma unroll
        for (int e = 0; e < NEXP; e++) if (e != e0 && acc[e] > v1) { v1 = acc[e]; e1 = e; }
        float ew = expf(v1 - v0);
        float inv = 1.f / (1.f + ew);
        g_top_idx[t * 2]     = e0;
        g_top_idx[t * 2 + 1] = e1;
        g_top_w[t * 2]       = inv;
        g_top_w[t * 2 + 1]   = ew * inv;
        float p[NEXP], s = 0.f;
#pragma unroll
        for (int e = 0; e < NEXP; e++) { p[e] = expf(acc[e] - v0); s += p[e]; }
        float is = 1.f / s;
#pragma unroll
        for (int e = 0; e < NEXP; e++) g_probs[t * NEXP + e] = p[e] * is;
        atomicAdd(&g_counts[e0], 1);
        atomicAdd(&g_counts[e1], 1);
    }
}

// ---------------- 3. offsets ----------------
__global__ void off_k() {
    if (threadIdx.x == 0) {
        int o = 0;
#pragma unroll
        for (int e = 0; e < NEXP; e++) {
            g_off[e] = o;
            o += ((g_counts[e] + 127) >> 7) << 7;
        }
        g_off[NEXP] = o;
    }
}

// ---------------- 4. scatter ----------------
__global__ void scatter_k() {
    int i = blockIdx.x * blockDim.x + threadIdx.x;
    if (i >= NTOK * 2) return;
    int e = g_top_idx[i];
    int slot = g_off[e] + atomicAdd(&g_cursor[e], 1);
    g_pair_token[slot] = i >> 1;
    g_pair_slot[i] = slot;
}

// ---------------- 5. gather x -> slot order, bf16 hi/lo ----------------
__global__ void gatherx_k(const float* __restrict__ x) {
    int idx = blockIdx.x * blockDim.x + threadIdx.x;    // PMAX * 256 float4
    int slot = idx >> 8;
    if (slot >= PMAX) return;
    int j = idx & 255;
    int tok = g_pair_token[slot];
    float4 v = make_float4(0.f, 0.f, 0.f, 0.f);
    if (tok >= 0) v = ((const float4*)x)[(size_t)tok * 256 + j];
    size_t o = (size_t)slot * 512 + j * 2;
    split_store4(v, (__nv_bfloat162*)g_xh + o, (__nv_bfloat162*)g_xl + o);
}

// ---------------- A-tile stage loader: bf16 gmem -> SW128 SMEM cp.async --
__device__ __forceinline__ void stageA(unsigned smDst, const bf16* g, int stride, int tid) {
#pragma unroll
    for (int i = 0; i < 4; i++) {               // 128 rows * 8 segs = 1024
        int idx = (i << 8) | tid;
        int r = idx >> 3, s = idx & 7;
        unsigned bo = (unsigned)((r << 7) | (s << 4));
        cpa16(smDst + sw128(bo), g + (size_t)r * stride + (s << 3));
    }
}

// ---------------- 6. GEMM1 (fc1) fused: fp32-W split-on-stage + SiLU*val -
// Per CTA: 128 rows x 128 act cols. B smem rows: [gate 0..127 ; val 128..255].
__global__ __launch_bounds__(256, 1)
void gemm1_fused(const float* __restrict__ w1, const float* __restrict__ bias) {
    extern __shared__ char smem[];
    const int rows_total = g_off[NEXP];
    const int row0 = blockIdx.y * TM;
    const int n0   = blockIdx.x * 128;          // act col base (0..4095)
    if (row0 >= rows_total) return;

    int e = 0;
#pragma unroll
    for (int i = 0; i < NEXP; i++) if (g_off[i + 1] <= row0) e = i + 1;

    const bf16* Ah  = g_xh + (size_t)row0 * D_IN;
    const bf16* Al  = g_xl + (size_t)row0 * D_IN;
    const float* Bg32 = w1 + (size_t)e * H2 * D_IN + (size_t)n0 * D_IN;
    const float* Bv32 = w1 + (size_t)e * H2 * D_IN + (size_t)(n0 + HID) * D_IN;

    const int tid = threadIdx.x;
    const int lane = tid & 31, wid = tid >> 5;
    const int wm = (wid & 1) * 64;        // 2 warps in M
    const int wn = (wid >> 1) * 32;       // 4 warps in N
    const unsigned sb = smem_u32(smem);

    const unsigned aRow = wm + (lane & 15);
    const unsigned aKb  = (unsigned)(lane >> 4) << 4;
    const unsigned bRow = wn + (lane & 7) + ((unsigned)(lane >> 4) << 3);
    const unsigned bKb  = (unsigned)((lane >> 3) & 1) << 4;

    float accg[4][4][4], accv[4][4][4];
#pragma unroll
    for (int mi = 0; mi < 4; mi++)
#pragma unroll
        for (int ni = 0; ni < 4; ni++)
#pragma unroll
            for (int j = 0; j < 4; j++) { accg[mi][ni][j] = 0.f; accv[mi][ni][j] = 0.f; }

    const int T = D_IN / KC;   // 16
    const int tg = tid >> 4, cs = tid & 15;    // B-load lane mapping

    // prologue: A chunk0 via cp.async; B chunk0 via LDG->split->STS
    {
        stageA(sb,          Ah, D_IN, tid);
        stageA(sb + A_TILE, Al, D_IN, tid);
        asm volatile("cp.async.commit_group;" ::: "memory");
        const unsigned bh0 = sb + 2 * A_TILE, bl0 = bh0 + B_TILE;
#pragma unroll
        for (int s = 0; s < 4; s++) {
            float4 bv[4];
#pragma unroll
            for (int j = 0; j < 4; j++) {
                int br = s * 64 + j * 16 + tg;
                const float* src = (s < 2) ? (Bg32 + (size_t)br * D_IN)
                                           : (Bv32 + (size_t)(br - 128) * D_IN);
                bv[j] = *(const float4*)(src + cs * 4);
            }
#pragma unroll
            for (int j = 0; j < 4; j++) {
                int br = s * 64 + j * 16 + tg;
                unsigned sw = sw128((unsigned)(br * 128 + cs * 8));
                split4_sts(bv[j], bh0 + sw, bl0 + sw);
            }
        }
    }

    for (int kt = 0; kt < T; kt++) {
        const int buf = kt & 1, nbuf = buf ^ 1;
        const int kOff2 = (kt + 1) * KC;
        // RACE FIX (R9->R10): wait + barrier BEFORE touching nbuf. All warps
        // must be done reading nbuf's A/B (it was the live buffer last iter)
        // before any cp.async or STS writes it.
        asm volatile("cp.async.wait_group 0;" ::: "memory");
        __syncthreads();
        if (kt + 1 < T) {
            stageA(sb + nbuf * STAGE,          Ah + kOff2, D_IN, tid);
            stageA(sb + nbuf * STAGE + A_TILE, Al + kOff2, D_IN, tid);
            asm volatile("cp.async.commit_group;" ::: "memory");
        }

        const unsigned sAh = sb + buf * STAGE;
        const unsigned sAl = sAh + A_TILE;
        const unsigned sBh = sAl + A_TILE;     // 256 rows: gate then val
        const unsigned sBl = sBh + B_TILE;
        const unsigned nBh = sb + nbuf * STAGE + 2 * A_TILE;
        const unsigned nBl = nBh + B_TILE;

#pragma unroll
        for (int s = 0; s < 4; s++) {
            // prefetch B sub-batch s of chunk kt+1 into regs
            float4 bv[4];
            if (kt + 1 < T) {
#pragma unroll
                for (int j = 0; j < 4; j++) {
                    int br = s * 64 + j * 16 + tg;
                    const float* src = (s < 2) ? (Bg32 + (size_t)br * D_IN)
                                               : (Bv32 + (size_t)(br - 128) * D_IN);
                    bv[j] = *(const float4*)(src + kOff2 + cs * 4);
                }
            }
            const unsigned kb = s * 32;
            unsigned ra[4][4], rgh[2][4], rvh[2][4], rx[2][4];
#pragma unroll
            for (int mi = 0; mi < 4; mi++)
                ldm4(ra[mi], sAh + sw128((aRow + mi * 16) * 128 + kb + aKb));
#pragma unroll
            for (int g = 0; g < 2; g++) {
                ldm4(rgh[g], sBh + sw128((bRow + g * 16) * 128 + kb + bKb));
                ldm4(rvh[g], sBh + sw128((128 + bRow + g * 16) * 128 + kb + bKb));
            }
            // Ah*Bh (gate + val)
#pragma unroll
            for (int mi = 0; mi < 4; mi++)
#pragma unroll
                for (int ni = 0; ni < 4; ni++) {
                    MMA(accg[mi][ni], ra[mi], &rgh[ni >> 1][(ni & 1) * 2]);
                    MMA(accv[mi][ni], ra[mi], &rvh[ni >> 1][(ni & 1) * 2]);
                }
            // Ah*Bl
#pragma unroll
            for (int g = 0; g < 2; g++)
                ldm4(rx[g], sBl + sw128((bRow + g * 16) * 128 + kb + bKb));
#pragma unroll
            for (int mi = 0; mi < 4; mi++)
#pragma unroll
                for (int ni = 0; ni < 4; ni++)
                    MMA(accg[mi][ni], ra[mi], &rx[ni >> 1][(ni & 1) * 2]);
#pragma unroll
            for (int g = 0; g < 2; g++)
                ldm4(rx[g], sBl + sw128((128 + bRow + g * 16) * 128 + kb + bKb));
#pragma unroll
            for (int mi = 0; mi < 4; mi++)
#pragma unroll
                for (int ni = 0; ni < 4; ni++)
                    MMA(accv[mi][ni], ra[mi], &rx[ni >> 1][(ni & 1) * 2]);
            // Al*Bh
#pragma unroll
            for (int mi = 0; mi < 4; mi++)
                ldm4(ra[mi], sAl + sw128((aRow + mi * 16) * 128 + kb + aKb));
#pragma unroll
            for (int mi = 0; mi < 4; mi++)
#pragma unroll
                for (int ni = 0; ni < 4; ni++) {
                    MMA(accg[mi][ni], ra[mi], &rgh[ni >> 1][(ni & 1) * 2]);
                    MMA(accv[mi][ni], ra[mi], &rvh[ni >> 1][(ni & 1) * 2]);
                }
            // store B sub-batch s into next buffer (safe: past this iter's barrier,
            // nbuf is exclusively write-owned until next iter's barrier)
            if (kt + 1 < T) {
#pragma unroll
                for (int j = 0; j < 4; j++) {
                    int br = s * 64 + j * 16 + tg;
                    unsigned sw = sw128((unsigned)(br * 128 + cs * 8));
                    split4_sts(bv[j], nBh + sw, nBl + sw);
                }
            }
        }
    }

    // epilogue: silu(g+bg)*(v+bv) -> bf16 hi/lo -> g_ah/g_al
    const float* bg = bias + (size_t)e * H2 + n0;
    const float* bvp = bg + HID;
    const int cr = lane >> 2;
    const int cc = (lane & 3) * 2;
#pragma unroll
    for (int mi = 0; mi < 4; mi++) {
        const int r0 = row0 + wm + mi * 16 + cr;
#pragma unroll
        for (int ni = 0; ni < 4; ni++) {
            const int col = wn + ni * 8 + cc;
            const float bg0 = bg[col], bg1 = bg[col + 1];
            const float bv0 = bvp[col], bv1 = bvp[col + 1];
            const size_t gc = (size_t)(n0 + col);
            {
                float a0 = silu(accg[mi][ni][0] + bg0) * (accv[mi][ni][0] + bv0);
                float a1 = silu(accg[mi][ni][1] + bg1) * (accv[mi][ni][1] + bv1);
                split2(a0, a1,
                       (__nv_bfloat162*)(g_ah + (size_t)r0 * HID + gc),
                       (__nv_bfloat162*)(g_al + (size_t)r0 * HID + gc));
            }
            {
                float a0 = silu(accg[mi][ni][2] + bg0) * (accv[mi][ni][2] + bv0);
                float a1 = silu(accg[mi][ni][3] + bg1) * (accv[mi][ni][3] + bv1);
                split2(a0, a1,
                       (__nv_bfloat162*)(g_ah + (size_t)(r0 + 8) * HID + gc),
                       (__nv_bfloat162*)(g_al + (size_t)(r0 + 8) * HID + gc));
            }
        }
    }
}

// ---------------- 7. GEMM2 (fc2): fp32-W split-on-stage, 128x256 tile ----
__global__ __launch_bounds__(256, 1)
void gemm2_mma(const float* __restrict__ w2, const float* __restrict__ bias) {
    extern __shared__ char smem[];
    const int KDIM = HID, NCOLS = D_IN;
    const int rows_total = g_off[NEXP];
    const int row0 = blockIdx.y * TM;
    const int n0   = blockIdx.x * 256;
    if (row0 >= rows_total) return;

    int e = 0;
#pragma unroll
    for (int i = 0; i < NEXP; i++) if (g_off[i + 1] <= row0) e = i + 1;

    const bf16* Ah = g_ah + (size_t)row0 * KDIM;
    const bf16* Al = g_al + (size_t)row0 * KDIM;
    const float* B32 = w2 + ((size_t)e * NCOLS + n0) * KDIM;

    const int tid = threadIdx.x;
    const int lane = tid & 31, wid = tid >> 5;
    const int wm = (wid & 1) * 64;
    const int wn = (wid >> 1) * 64;
    const unsigned sb = smem_u32(smem);

    const unsigned aRow = wm + (lane & 15);
    const unsigned aKb  = (unsigned)(lane >> 4) << 4;
    const unsigned bRow = wn + (lane & 7) + ((unsigned)(lane >> 4) << 3);
    const unsigned bKb  = (unsigned)((lane >> 3) & 1) << 4;

    float acc[4][8][4];
#pragma unroll
    for (int mi = 0; mi < 4; mi++)
#pragma unroll
        for (int ni = 0; ni < 8; ni++)
#pragma unroll
            for (int j = 0; j < 4; j++) acc[mi][ni][j] = 0.f;

    const int T = KDIM / KC;   // 64
    const int tg = tid >> 4, cs = tid & 15;

    {
        stageA(sb,          Ah, KDIM, tid);
        stageA(sb + A_TILE, Al, KDIM, tid);
        asm volatile("cp.async.commit_group;" ::: "memory");
        const unsigned bh0 = sb + 2 * A_TILE, bl0 = bh0 + B_TILE;
#pragma unroll
        for (int s = 0; s < 4; s++) {
            float4 bv[4];
#pragma unroll
            for (int j = 0; j < 4; j++) {
                int br = s * 64 + j * 16 + tg;
                bv[j] = *(const float4*)(B32 + (size_t)br * KDIM + cs * 4);
            }
#pragma unroll
            for (int j = 0; j < 4; j++) {
                int br = s * 64 + j * 16 + tg;
                unsigned sw = sw128((unsigned)(br * 128 + cs * 8));
                split4_sts(bv[j], bh0 + sw, bl0 + sw);
            }
        }
    }

    for (int kt = 0; kt < T; kt++) {
        const int buf = kt & 1, nbuf = buf ^ 1;
        const int kOff2 = (kt + 1) * KC;
        // RACE FIX: wait + barrier BEFORE writing nbuf (see gemm1)
        asm volatile("cp.async.wait_group 0;" ::: "memory");
        __syncthreads();
        if (kt + 1 < T) {
            stageA(sb + nbuf * STAGE,          Ah + kOff2, KDIM, tid);
            stageA(sb + nbuf * STAGE + A_TILE, Al + kOff2, KDIM, tid);
            asm volatile("cp.async.commit_group;" ::: "memory");
        }

        const unsigned sAh = sb + buf * STAGE;
        const unsigned sAl = sAh + A_TILE;
        const unsigned sBh = sAl + A_TILE;
        const unsigned sBl = sBh + B_TILE;
        const unsigned nBh = sb + nbuf * STAGE + 2 * A_TILE;
        const unsigned nBl = nBh + B_TILE;

#pragma unroll
        for (int s = 0; s < 4; s++) {
            float4 bv[4];
            if (kt + 1 < T) {
#pragma unroll
                for (int j = 0; j < 4; j++) {
                    int br = s * 64 + j * 16 + tg;
                    bv[j] = *(const float4*)(B32 + (size_t)br * KDIM + kOff2 + cs * 4);
                }
            }
            const unsigned kb = s * 32;
            unsigned ra[4][4], rb[4][4], rc[4][4];
#pragma unroll
            for (int mi = 0; mi < 4; mi++)
                ldm4(ra[mi], sAh + sw128((aRow + mi * 16) * 128 + kb + aKb));
#pragma unroll
            for (int g = 0; g < 4; g++)
                ldm4(rb[g], sBh + sw128((bRow + g * 16) * 128 + kb + bKb));
#pragma unroll
            for (int mi = 0; mi < 4; mi++)
#pragma unroll
                for (int ni = 0; ni < 8; ni++)
                    MMA(acc[mi][ni], ra[mi], &rb[ni >> 1][(ni & 1) * 2]);
#pragma unroll
            for (int g = 0; g < 4; g++)
                ldm4(rc[g], sBl + sw128((bRow + g * 16) * 128 + kb + bKb));
#pragma unroll
            for (int mi = 0; mi < 4; mi++)
#pragma unroll
                for (int ni = 0; ni < 8; ni++)
                    MMA(acc[mi][ni], ra[mi], &rc[ni >> 1][(ni & 1) * 2]);
#pragma unroll
            for (int mi = 0; mi < 4; mi++)
                ldm4(ra[mi], sAl + sw128((aRow + mi * 16) * 128 + kb + aKb));
#pragma unroll
            for (int mi = 0; mi < 4; mi++)
#pragma unroll
                for (int ni = 0; ni < 8; ni++)
                    MMA(acc[mi][ni], ra[mi], &rb[ni >> 1][(ni & 1) * 2]);
            if (kt + 1 < T) {
#pragma unroll
                for (int j = 0; j < 4; j++) {
                    int br = s * 64 + j * 16 + tg;
                    unsigned sw = sw128((unsigned)(br * 128 + cs * 8));
                    split4_sts(bv[j], nBh + sw, nBl + sw);
                }
            }
        }
    }

    const float* brow = bias + (size_t)e * NCOLS + n0;
    const int cr = lane >> 2;
    const int cc = (lane & 3) * 2;
#pragma unroll
    for (int mi = 0; mi < 4; mi++) {
        const int r0 = row0 + wm + mi * 16 + cr;
#pragma unroll
        for (int ni = 0; ni < 8; ni++) {
            const int col = wn + ni * 8 + cc;
            const float b0 = brow[col], b1 = brow[col + 1];
            float* p0 = g_yp + (size_t)r0 * NCOLS + n0 + col;
            *(float2*)p0 = make_float2(acc[mi][ni][0] + b0, acc[mi][ni][1] + b1);
            float* p1 = p0 + (size_t)8 * NCOLS;
            *(float2*)p1 = make_float2(acc[mi][ni][2] + b0, acc[mi][ni][3] + b1);
        }
    }
}

// ---------------- 8. combine ----------------
__global__ void combine_k(float* __restrict__ out) {
    int idx = blockIdx.x * blockDim.x + threadIdx.x;
    if (idx >= NTOK * 256) return;
    int t = idx >> 8, j4 = idx & 255;
    int s0 = g_pair_slot[t * 2], s1 = g_pair_slot[t * 2 + 1];
    float w0 = g_top_w[t * 2], w1 = g_top_w[t * 2 + 1];
    float4 y0 = ((const float4*)g_yp)[(size_t)s0 * 256 + j4];
    float4 y1 = ((const float4*)g_yp)[(size_t)s1 * 256 + j4];
    float4 r;
    r.x = w0 * y0.x + w1 * y1.x;
    r.y = w0 * y0.y + w1 * y1.y;
    r.z = w0 * y0.z + w1 * y1.z;
    r.w = w0 * y0.w + w1 * y1.w;
    ((float4*)out)[idx] = r;
}

// ---------------- 9. aux loss ----------------
__global__ void aux_k(float* __restrict__ out, int out_size) {
    __shared__ float red[256];
    float local[NEXP];
#pragma unroll
    for (int e = 0; e < NEXP; e++) local[e] = 0.f;
    for (int t = threadIdx.x; t < NTOK; t += 256)
#pragma unroll
        for (int e = 0; e < NEXP; e++) local[e] += g_probs[t * NEXP + e];
    float aux = 0.f;
    for (int e = 0; e < NEXP; e++) {
        red[threadIdx.x] = local[e];
        __syncthreads();
        for (int s = 128; s; s >>= 1) {
            if (threadIdx.x < s) red[threadIdx.x] += red[threadIdx.x + s];
            __syncthreads();
        }
        if (threadIdx.x == 0)
            aux += ((float)g_counts[e] / (float)NTOK) * (red[0] / (float)NTOK);
        __syncthreads();
    }
    if (threadIdx.x == 0 && out_size > NTOK * D_IN)
        out[NTOK * D_IN] = (float)NEXP * aux;
}

// ---------------- launch ----------------
extern "C" void kernel_launch(void* const* d_in, const int* in_sizes, int n_in,
                              void* d_out, int out_size) {
    const float* x    = (const float*)d_in[0];
    const float* Wg   = (const float*)d_in[1];
    const float* fc1w = (const float*)d_in[2];
    const float* fc1b = (const float*)d_in[3];
    const float* fc2w = (const float*)d_in[4];
    const float* fc2b = (const float*)d_in[5];
    float* out = (float*)d_out;

    cudaFuncSetAttribute(gemm1_fused, cudaFuncAttributeMaxDynamicSharedMemorySize, SMEM_GEMM);
    cudaFuncSetAttribute(gemm2_mma,   cudaFuncAttributeMaxDynamicSharedMemorySize, SMEM_GEMM);

    init_k<<<(PMAX + 255) / 256, 256>>>();
    gate_k<<<NTOK / 4, 128>>>(x, Wg);
    off_k<<<1, 32>>>();
    scatter_k<<<(NTOK * 2 + 255) / 256, 256>>>();
    gatherx_k<<<PMAX, 256>>>(x);

    gemm1_fused<<<dim3(HID / 128, PMAX / TM), 256, SMEM_GEMM>>>(fc1w, fc1b);
    gemm2_mma  <<<dim3(D_IN / 256, PMAX / TM), 256, SMEM_GEMM>>>(fc2w, fc2b);

    combine_k<<<(NTOK * 256) / 256, 256>>>(out);
    aux_k<<<1, 256>>>(out, out_size);
}